// round 3
// baseline (speedup 1.0000x reference)
#include <cuda_runtime.h>

#define THETA 0.9999f

// Exact IF-neuron spike-rate over 50 steps with constant drive a, soft reset.
// Matches the reference f32 scan bit-for-bit in the nontrivial range.
__device__ __forceinline__ float rate50(float a) {
    if (a <= 0.0f) return 0.0f;
    if (a >= THETA) return 1.0f;   // spikes every step (exact: v>=0 pre-add => v+a>=theta)
    float v = 0.0f;
    float cnt = 0.0f;
    for (int t = 0; t < 50; ++t) {
        v += a;
        if (v >= THETA) { v -= THETA; cnt += 1.0f; }
    }
    return cnt / 50.0f;
}

// Shared layout (floats), with buffer overlay:
//   A [0,184)       : mx (padded, data at h+1), later 32 warp-reduction partials
//   B [184,3256)    : r1 (16 rows stride 184, data at h+1, zero pads)
//                     then r3 (32 rows stride 96, data at h+1, zero pads)
//   C [3256,8888)   : r2 (32 rows stride 176)
//                     then r4 (32 rows stride 88)
#define SM_TOTAL 8888
#define B_OFF 184
#define C_OFF 3256

__global__ __launch_bounds__(256, 2)
void catnet_kernel(const float* __restrict__ x,
                   const float* __restrict__ w1, const float* __restrict__ b1,
                   const float* __restrict__ w2, const float* __restrict__ b2,
                   const float* __restrict__ w3, const float* __restrict__ b3,
                   const float* __restrict__ wf, const float* __restrict__ bf,
                   float* __restrict__ out) {
    __shared__ float sm[SM_TOTAL];
    float* A = sm;
    float* B = sm + B_OFF;
    float* C = sm + C_OFF;
    const int tid = threadIdx.x;
    const int n = blockIdx.x;

    // zero all shared (covers all pad positions for mx and r1)
    for (int i = tid; i < SM_TOTAL; i += 256) sm[i] = 0.0f;
    __syncthreads();

    // ---- stage 0: mean over time: x[n,0,h,0,t] -> A[h+1] ----
    const float* xn = x + (long)n * (180 * 50);
    for (int h = tid; h < 180; h += 256) {
        const float* xp = xn + h * 50;
        float s = 0.0f;
        #pragma unroll
        for (int t = 0; t < 50; ++t) s += xp[t];
        A[h + 1] = s / 50.0f;
    }
    __syncthreads();

    // ---- stage 1: conv (16,1,3) pad 1 + rate -> B (r1, stride 184) ----
    for (int idx = tid; idx < 16 * 180; idx += 256) {
        int o = idx / 180, h = idx - o * 180;
        float a = b1[o]
                + A[h]     * w1[o * 3]
                + A[h + 1] * w1[o * 3 + 1]
                + A[h + 2] * w1[o * 3 + 2];
        B[o * 184 + h + 1] = rate50(a);
    }
    __syncthreads();

    // ---- stage 2: conv (32,16,9) pad 1 + rate -> C (r2, stride 176) ----
    // thread -> (o = tid/8, h-block of 22); outputs h in [0,176) (174 valid, 2 garbage never read)
    {
        int o = tid >> 3;
        int h0 = (tid & 7) * 22;
        float acc[22];
        float bb = b2[o];
        #pragma unroll
        for (int j = 0; j < 22; ++j) acc[j] = bb;
        for (int c = 0; c < 16; ++c) {
            float win[30];
            const float* row = B + c * 184 + h0;
            #pragma unroll
            for (int j = 0; j < 30; ++j) win[j] = row[j];
            const float* wp = w2 + (o * 16 + c) * 9;
            #pragma unroll
            for (int k = 0; k < 9; ++k) {
                float wv = wp[k];
                #pragma unroll
                for (int j = 0; j < 22; ++j) acc[j] += win[j + k] * wv;
            }
        }
        #pragma unroll
        for (int j = 0; j < 22; ++j) C[o * 176 + h0 + j] = rate50(acc[j]);
    }
    __syncthreads();

    // ---- stage 3: sum-pool(2)*1.1 + rate -> B (r3, stride 96, data at h+1) ----
    for (int idx = tid; idx < 32 * 87; idx += 256) {
        int o = idx / 87, h = idx - o * 87;
        float a = 1.1f * (C[o * 176 + 2 * h] + C[o * 176 + 2 * h + 1]);
        B[o * 96 + h + 1] = rate50(a);
    }
    // zero r3 pads (region B previously held r1 data) + zero reduction scratch
    if (tid < 32) {
        B[tid * 96] = 0.0f;
        #pragma unroll
        for (int j = 88; j < 96; ++j) B[tid * 96 + j] = 0.0f;
        A[tid] = 0.0f;
    }
    __syncthreads();

    // ---- stage 4: conv (32,32,7) pad 1 + rate -> C (r4, stride 88) ----
    // thread -> (o = tid/8, h-block of 11); outputs h in [0,88) (83 valid)
    {
        int o = tid >> 3;
        int h0 = (tid & 7) * 11;
        float acc[11];
        float bb = b3[o];
        #pragma unroll
        for (int j = 0; j < 11; ++j) acc[j] = bb;
        for (int c = 0; c < 32; ++c) {
            float win[17];
            const float* row = B + c * 96 + h0;
            #pragma unroll
            for (int j = 0; j < 17; ++j) win[j] = row[j];
            const float* wp = w3 + (o * 32 + c) * 7;
            #pragma unroll
            for (int k = 0; k < 7; ++k) {
                float wv = wp[k];
                #pragma unroll
                for (int j = 0; j < 11; ++j) acc[j] += win[j + k] * wv;
            }
        }
        #pragma unroll
        for (int j = 0; j < 11; ++j) C[o * 88 + h0 + j] = rate50(acc[j]);
    }
    __syncthreads();

    // ---- stage 5: dense out[n,o] = sum_{c,h} r4[c,h]*wf[o,c,h] + bf[o] ----
    {
        float p0 = 0.f, p1 = 0.f, p2 = 0.f, p3 = 0.f;
        for (int idx = tid; idx < 32 * 83; idx += 256) {
            int c = idx / 83, h = idx - c * 83;
            float v = C[c * 88 + h];
            int wi = c * 83 + h;
            p0 += v * wf[wi];
            p1 += v * wf[wi + 2656];
            p2 += v * wf[wi + 2 * 2656];
            p3 += v * wf[wi + 3 * 2656];
        }
        #pragma unroll
        for (int off = 16; off; off >>= 1) {
            p0 += __shfl_down_sync(0xffffffffu, p0, off);
            p1 += __shfl_down_sync(0xffffffffu, p1, off);
            p2 += __shfl_down_sync(0xffffffffu, p2, off);
            p3 += __shfl_down_sync(0xffffffffu, p3, off);
        }
        int lane = tid & 31, wid = tid >> 5;
        if (lane == 0) {
            A[wid * 4 + 0] = p0;
            A[wid * 4 + 1] = p1;
            A[wid * 4 + 2] = p2;
            A[wid * 4 + 3] = p3;
        }
    }
    __syncthreads();
    if (tid < 4) {
        float s = bf[tid];
        #pragma unroll
        for (int w = 0; w < 8; ++w) s += A[w * 4 + tid];
        out[n * 4 + tid] = s;
    }
}

extern "C" void kernel_launch(void* const* d_in, const int* in_sizes, int n_in,
                              void* d_out, int out_size) {
    const float* x  = (const float*)d_in[0];
    const float* w1 = (const float*)d_in[1];
    const float* b1 = (const float*)d_in[2];
    const float* w2 = (const float*)d_in[3];
    const float* b2 = (const float*)d_in[4];
    const float* w3 = (const float*)d_in[5];
    const float* b3 = (const float*)d_in[6];
    const float* wf = (const float*)d_in[7];
    const float* bf = (const float*)d_in[8];
    float* out = (float*)d_out;

    int n = in_sizes[0] / (180 * 50);   // batch size (256)
    catnet_kernel<<<n, 256>>>(x, w1, b1, w2, b2, w3, b3, wf, bf, out);
}

// round 5
// speedup vs baseline: 1.7027x; 1.7027x over previous
#include <cuda_runtime.h>

#define THETA 0.9999f

// Exact IF-neuron spike-rate over 50 steps with constant drive a, soft reset.
// Closed form: count = floor(50*a/theta) for 0<a<theta (exact in real arithmetic).
// The reference computes this with an f32 scan; its rounding can only change the
// count when 50*a/theta is within ~6e-6 of an integer, so we run the exact f32
// sim only inside a +-1e-4 band around integers (prob ~2e-4 per call).
__device__ __forceinline__ float rate50(float a) {
    if (a <= 0.0f) return 0.0f;
    if (a >= THETA) return 1.0f;
    float u = a * (50.0f / THETA);
    float k = floorf(u);
    float d = u - k;
    if (d > 1e-4f && d < 0.9999f) {
        return k * 0.02f;
    }
    // boundary: bit-exact 50-step f32 simulation (matches reference scan)
    float v = 0.0f;
    float cnt = 0.0f;
    #pragma unroll
    for (int t = 0; t < 50; ++t) {
        v += a;
        if (v >= THETA) { v -= THETA; cnt += 1.0f; }
    }
    return cnt * 0.02f;
}

// Shared layout (floats), with buffer overlay:
//   A [0,184)       : mx (padded, data at h+1), later 32 warp-reduction partials
//   B [184,3256)    : r1 (16 rows stride 184, data at h+1, zero pads)
//                     then r3 (32 rows stride 96, data at h+1, zero pads)
//   C [3256,8888)   : r2 (32 rows stride 176)
//                     then r4 (32 rows stride 88)
#define SM_TOTAL 8888
#define B_OFF 184
#define C_OFF 3256

__global__ __launch_bounds__(256, 2)
void catnet_kernel(const float* __restrict__ x,
                   const float* __restrict__ w1, const float* __restrict__ b1,
                   const float* __restrict__ w2, const float* __restrict__ b2,
                   const float* __restrict__ w3, const float* __restrict__ b3,
                   const float* __restrict__ wf, const float* __restrict__ bf,
                   float* __restrict__ out) {
    __shared__ float sm[SM_TOTAL];
    float* A = sm;
    float* B = sm + B_OFF;
    float* C = sm + C_OFF;
    const int tid = threadIdx.x;
    const int n = blockIdx.x;

    // zero all shared (covers all pad positions for mx and r1)
    for (int i = tid; i < SM_TOTAL; i += 256) sm[i] = 0.0f;
    __syncthreads();

    // ---- stage 0: mean over time: x[n,0,h,0,t] -> A[h+1] ----
    // 50 floats per row, 200B row stride -> float2 aligned (200 % 8 == 0)
    const float2* xn2 = (const float2*)(x + (long)n * (180 * 50));
    for (int h = tid; h < 180; h += 256) {
        const float2* xp = xn2 + h * 25;
        float s0 = 0.0f, s1 = 0.0f;
        #pragma unroll
        for (int t = 0; t < 25; ++t) {
            float2 v = xp[t];
            s0 += v.x; s1 += v.y;
        }
        A[h + 1] = (s0 + s1) / 50.0f;
    }
    __syncthreads();

    // ---- stage 1: conv (16,1,3) pad 1 + rate -> B (r1, stride 184) ----
    for (int idx = tid; idx < 16 * 180; idx += 256) {
        int o = idx / 180, h = idx - o * 180;
        float a = b1[o]
                + A[h]     * w1[o * 3]
                + A[h + 1] * w1[o * 3 + 1]
                + A[h + 2] * w1[o * 3 + 2];
        B[o * 184 + h + 1] = rate50(a);
    }
    __syncthreads();

    // ---- stage 2: conv (32,16,9) pad 1 + rate -> C (r2, stride 176) ----
    // thread -> (o = tid/8, h-block of 22); outputs h in [0,176) (174 valid, 2 garbage never read)
    {
        int o = tid >> 3;
        int h0 = (tid & 7) * 22;
        float acc[22];
        float bb = b2[o];
        #pragma unroll
        for (int j = 0; j < 22; ++j) acc[j] = bb;
        for (int c = 0; c < 16; ++c) {
            float win[30];
            const float* row = B + c * 184 + h0;
            #pragma unroll
            for (int j = 0; j < 30; ++j) win[j] = row[j];
            const float* wp = w2 + (o * 16 + c) * 9;
            #pragma unroll
            for (int k = 0; k < 9; ++k) {
                float wv = wp[k];
                #pragma unroll
                for (int j = 0; j < 22; ++j) acc[j] += win[j + k] * wv;
            }
        }
        #pragma unroll
        for (int j = 0; j < 22; ++j) C[o * 176 + h0 + j] = rate50(acc[j]);
    }
    __syncthreads();

    // ---- stage 3: sum-pool(2)*1.1 + rate -> B (r3, stride 96, data at h+1) ----
    for (int idx = tid; idx < 32 * 87; idx += 256) {
        int o = idx / 87, h = idx - o * 87;
        float a = 1.1f * (C[o * 176 + 2 * h] + C[o * 176 + 2 * h + 1]);
        B[o * 96 + h + 1] = rate50(a);
    }
    // zero r3 pads (region B previously held r1 data) + zero reduction scratch
    if (tid < 32) {
        B[tid * 96] = 0.0f;
        #pragma unroll
        for (int j = 88; j < 96; ++j) B[tid * 96 + j] = 0.0f;
        A[tid] = 0.0f;
    }
    __syncthreads();

    // ---- stage 4: conv (32,32,7) pad 1 + rate -> C (r4, stride 88) ----
    // thread -> (o = tid/8, h-block of 11); outputs h in [0,88) (83 valid)
    {
        int o = tid >> 3;
        int h0 = (tid & 7) * 11;
        float acc[11];
        float bb = b3[o];
        #pragma unroll
        for (int j = 0; j < 11; ++j) acc[j] = bb;
        for (int c = 0; c < 32; ++c) {
            float win[17];
            const float* row = B + c * 96 + h0;
            #pragma unroll
            for (int j = 0; j < 17; ++j) win[j] = row[j];
            const float* wp = w3 + (o * 32 + c) * 7;
            #pragma unroll
            for (int k = 0; k < 7; ++k) {
                float wv = wp[k];
                #pragma unroll
                for (int j = 0; j < 11; ++j) acc[j] += win[j + k] * wv;
            }
        }
        #pragma unroll
        for (int j = 0; j < 11; ++j) C[o * 88 + h0 + j] = rate50(acc[j]);
    }
    __syncthreads();

    // ---- stage 5: dense out[n,o] = sum_{c,h} r4[c,h]*wf[o,c,h] + bf[o] ----
    {
        float p0 = 0.f, p1 = 0.f, p2 = 0.f, p3 = 0.f;
        for (int idx = tid; idx < 32 * 83; idx += 256) {
            int c = idx / 83, h = idx - c * 83;
            float v = C[c * 88 + h];
            int wi = c * 83 + h;
            p0 += v * wf[wi];
            p1 += v * wf[wi + 2656];
            p2 += v * wf[wi + 2 * 2656];
            p3 += v * wf[wi + 3 * 2656];
        }
        #pragma unroll
        for (int off = 16; off; off >>= 1) {
            p0 += __shfl_down_sync(0xffffffffu, p0, off);
            p1 += __shfl_down_sync(0xffffffffu, p1, off);
            p2 += __shfl_down_sync(0xffffffffu, p2, off);
            p3 += __shfl_down_sync(0xffffffffu, p3, off);
        }
        int lane = tid & 31, wid = tid >> 5;
        if (lane == 0) {
            A[wid * 4 + 0] = p0;
            A[wid * 4 + 1] = p1;
            A[wid * 4 + 2] = p2;
            A[wid * 4 + 3] = p3;
        }
    }
    __syncthreads();
    if (tid < 4) {
        float s = bf[tid];
        #pragma unroll
        for (int w = 0; w < 8; ++w) s += A[w * 4 + tid];
        out[n * 4 + tid] = s;
    }
}

extern "C" void kernel_launch(void* const* d_in, const int* in_sizes, int n_in,
                              void* d_out, int out_size) {
    const float* x  = (const float*)d_in[0];
    const float* w1 = (const float*)d_in[1];
    const float* b1 = (const float*)d_in[2];
    const float* w2 = (const float*)d_in[3];
    const float* b2 = (const float*)d_in[4];
    const float* w3 = (const float*)d_in[5];
    const float* b3 = (const float*)d_in[6];
    const float* wf = (const float*)d_in[7];
    const float* bf = (const float*)d_in[8];
    float* out = (float*)d_out;

    int n = in_sizes[0] / (180 * 50);   // batch size (256)
    catnet_kernel<<<n, 256>>>(x, w1, b1, w2, b2, w3, b3, wf, bf, out);
}